// round 1
// baseline (speedup 1.0000x reference)
#include <cuda_runtime.h>
#include <math.h>

// ---------------- problem constants ----------------
#define B 2
#define C 192
#define HEADS 6
#define HD 32
#define ZP 32
#define NPOS (B*ZP*ZP*ZP)          // 65536 token positions
#define NW 256                      // windows per batch
#define NTOK 128                    // tokens per window
#define DEPTH 4
#define TBL 675                     // (2*2-1)*(15)*(15)

// ---------------- scratch (device globals; allocation-free) ----------------
__device__ float g_e  [(size_t)NPOS * C];        // residual stream
__device__ float g_w  [(size_t)NPOS * C];        // LN / windowed scratch
__device__ float g_qkv[(size_t)NPOS * 3 * C];    // qkv (also recon gemm out)
__device__ float g_o  [(size_t)NPOS * C];        // attention output (window layout)
__device__ float g_h  [(size_t)NPOS * 4 * C];    // mlp hidden (also patch gather)
__device__ float g_pewT[128 * C];                // transposed patch-embed weight
__device__ float g_zeros[128];                   // zero bias (zero-initialized)

// ---------------- generic tiled fp32 GEMM ----------------
// C[M,N] = act(A[M,K] @ B[K,N] + bias[N])  (+= if BETA)
template<int ACT, int BETA>
__global__ __launch_bounds__(256)
void gemm_kernel(const float* __restrict__ A, const float* __restrict__ Bm,
                 const float* __restrict__ bias, float* __restrict__ Cm,
                 int M, int N, int K)
{
    __shared__ float As[16][64];
    __shared__ float Bs[16][68];
    const int bm = blockIdx.y << 6;
    const int bn = blockIdx.x << 6;
    const int tid = threadIdx.x;
    const int tx = tid & 15, ty = tid >> 4;
    float acc[4][4] = {};
    for (int k0 = 0; k0 < K; k0 += 16) {
#pragma unroll
        for (int j = 0; j < 4; j++) {
            int i = tid * 4 + j;
            As[i & 15][i >> 4] = A[(size_t)(bm + (i >> 4)) * K + k0 + (i & 15)];
        }
#pragma unroll
        for (int j = 0; j < 4; j++) {
            int i = tid + j * 256;
            Bs[i >> 6][i & 63] = Bm[(size_t)(k0 + (i >> 6)) * N + bn + (i & 63)];
        }
        __syncthreads();
#pragma unroll
        for (int kk = 0; kk < 16; kk++) {
            float a[4], b[4];
#pragma unroll
            for (int r = 0; r < 4; r++) a[r] = As[kk][(ty << 2) + r];
#pragma unroll
            for (int c = 0; c < 4; c++) b[c] = Bs[kk][(tx << 2) + c];
#pragma unroll
            for (int r = 0; r < 4; r++)
#pragma unroll
                for (int c = 0; c < 4; c++) acc[r][c] += a[r] * b[c];
        }
        __syncthreads();
    }
#pragma unroll
    for (int r = 0; r < 4; r++) {
        int row = bm + (ty << 2) + r;
#pragma unroll
        for (int c = 0; c < 4; c++) {
            int col = bn + (tx << 2) + c;
            float v = acc[r][c] + bias[col];
            if (ACT == 1) v = 0.5f * v * (1.0f + erff(v * 0.70710678118654752f));
            size_t oi = (size_t)row * N + col;
            if (BETA) Cm[oi] += v; else Cm[oi] = v;
        }
    }
}

// ---------------- LayerNorm (flat or window-partition layouts) ----------------
// mode: 0 = flat (dst[pos]=LN(src[pos])), 1 = window no-shift, 2 = window +roll
__global__ __launch_bounds__(192)
void ln_kernel(const float* __restrict__ src, float* __restrict__ dst,
               const float* __restrict__ g, const float* __restrict__ b, int mode)
{
    __shared__ float sb[20];
    int tok = blockIdx.x;
    int c = threadIdx.x;
    int spos;
    if (mode == 0) {
        spos = tok;
    } else {
        int n = tok & 127, wi = (tok >> 7) & 255, bb = tok >> 15;
        int zw = wi >> 4, hw = (wi >> 2) & 3, ww = wi & 3;
        int iz = n >> 6, ih = (n >> 3) & 7, iw = n & 7;
        int z = zw * 2 + iz, h = hw * 8 + ih, w = ww * 8 + iw;
        if (mode == 2) { z = (z + 1) & 31; h = (h + 4) & 31; w = (w + 4) & 31; }
        spos = ((bb * 32 + z) * 32 + h) * 32 + w;
    }
    float v = src[(size_t)spos * C + c];
    // block stats over 192 threads (6 warps)
    float s = v, s2 = v * v;
#pragma unroll
    for (int o = 16; o > 0; o >>= 1) {
        s  += __shfl_down_sync(0xffffffffu, s,  o);
        s2 += __shfl_down_sync(0xffffffffu, s2, o);
    }
    int wid = threadIdx.x >> 5;
    if ((threadIdx.x & 31) == 0) { sb[wid] = s; sb[8 + wid] = s2; }
    __syncthreads();
    if (threadIdx.x == 0) {
        float t = 0.f, t2 = 0.f;
        for (int i = 0; i < 6; i++) { t += sb[i]; t2 += sb[8 + i]; }
        float m = t * (1.0f / 192.0f);
        sb[16] = m;
        sb[17] = rsqrtf(t2 * (1.0f / 192.0f) - m * m + 1e-5f);
    }
    __syncthreads();
    float mean = sb[16], rstd = sb[17];
    dst[(size_t)tok * C + c] = (v - mean) * rstd * g[c] + b[c];
}

// ---------------- window attention: one block per (window, head) ----------------
__global__ __launch_bounds__(256)
void attn_kernel(const float* __restrict__ rpb, int shifted)
{
    extern __shared__ float sm[];
    float* Q  = sm;                 // 128 x 33
    float* Kt = Q  + 128 * 33;      // 128 x 33
    float* V  = Kt + 128 * 33;      // 128 x 33
    float* S  = V  + 128 * 33;      // 128 x 129
    const int win = blockIdx.x;     // 0..511 (b*256+wi)
    const int hh  = blockIdx.y;     // head
    const int tid = threadIdx.x;
    const float scale = 0.1767766952966369f; // 32^-0.5

    for (int e = tid; e < 128 * 32; e += 256) {
        int n = e >> 5, d = e & 31;
        size_t base = ((size_t)(win * 128 + n)) * (3 * C) + hh * 32 + d;
        Q [n * 33 + d] = g_qkv[base] * scale;
        Kt[n * 33 + d] = g_qkv[base + C];
        V [n * 33 + d] = g_qkv[base + 2 * C];
    }
    __syncthreads();

    int wloc = win & 255;
    int zw = wloc >> 4, hw = (wloc >> 2) & 3, ww = wloc & 3;

    for (int e = tid; e < 128 * 128; e += 256) {
        int n = e >> 7, m = e & 127;
        float acc = 0.f;
#pragma unroll
        for (int d = 0; d < 32; d++) acc += Q[n * 33 + d] * Kt[m * 33 + d];
        int zn = n >> 6, hn = (n >> 3) & 7, wn = n & 7;
        int zm = m >> 6, hm = (m >> 3) & 7, wm = m & 7;
        int idx = (zn - zm + 1) * 225 + (hn - hm + 7) * 15 + (wn - wm + 7);
        acc += rpb[idx * HEADS + hh];
        if (shifted) {
            int z1 = zw * 2 + zn, h1 = hw * 8 + hn, w1 = ww * 8 + wn;
            int z2 = zw * 2 + zm, h2 = hw * 8 + hm, w2 = ww * 8 + wm;
            int r1 = (z1 < 30 ? 0 : (z1 < 31 ? 1 : 2)) * 9
                   + (h1 < 24 ? 0 : (h1 < 28 ? 1 : 2)) * 3
                   + (w1 < 24 ? 0 : (w1 < 28 ? 1 : 2));
            int r2 = (z2 < 30 ? 0 : (z2 < 31 ? 1 : 2)) * 9
                   + (h2 < 24 ? 0 : (h2 < 28 ? 1 : 2)) * 3
                   + (w2 < 24 ? 0 : (w2 < 28 ? 1 : 2));
            if (r1 != r2) acc -= 100.0f;
        }
        S[n * 129 + m] = acc;
    }
    __syncthreads();

    if (tid < 128) {
        float mx = -1e30f;
        for (int m = 0; m < 128; m++) mx = fmaxf(mx, S[tid * 129 + m]);
        float sum = 0.f;
        for (int m = 0; m < 128; m++) {
            float p = expf(S[tid * 129 + m] - mx);
            S[tid * 129 + m] = p;
            sum += p;
        }
        float inv = 1.0f / sum;
        for (int m = 0; m < 128; m++) S[tid * 129 + m] *= inv;
    }
    __syncthreads();

    for (int e = tid; e < 128 * 32; e += 256) {
        int n = e >> 5, d = e & 31;
        float acc = 0.f;
#pragma unroll 8
        for (int m = 0; m < 128; m++) acc += S[n * 129 + m] * V[m * 33 + d];
        g_o[((size_t)(win * 128 + n)) * C + hh * 32 + d] = acc;
    }
}

// ---------------- window-merge + reverse roll + residual add ----------------
__global__ void unwin_add_kernel(float* __restrict__ e, const float* __restrict__ w, int shifted)
{
    int idx = blockIdx.x * blockDim.x + threadIdx.x;
    if (idx >= NPOS * C) return;
    int c = idx % C;
    int pos = idx / C;
    int ww2 = pos & 31, hh = (pos >> 5) & 31, z = (pos >> 10) & 31, b = pos >> 15;
    int sz = shifted ? 1 : 0, s2 = shifted ? 4 : 0;
    int z2 = (z - sz) & 31, h2 = (hh - s2) & 31, w2 = (ww2 - s2) & 31;
    int wi = ((z2 >> 1) << 4) | ((h2 >> 3) << 2) | (w2 >> 3);
    int n  = ((z2 & 1) << 6) | ((h2 & 7) << 3) | (w2 & 7);
    int tok = (b * 256 + wi) * 128 + n;
    e[idx] += w[(size_t)tok * C + c];
}

// ---------------- patch-embed gather: x -> (NPOS,128) ----------------
__global__ void gather_kernel(const float* __restrict__ x, float* __restrict__ xg)
{
    int idx = blockIdx.x * blockDim.x + threadIdx.x;
    if (idx >= NPOS * 128) return;
    int t = idx & 127, pos = idx >> 7;
    int w = pos & 31, h = (pos >> 5) & 31, z = (pos >> 10) & 31, b = pos >> 15;
    int c4 = t >> 5, i = (t >> 4) & 1, j = (t >> 2) & 3, k = t & 3;
    xg[idx] = x[((((size_t)b * 4 + c4) * 64 + 2 * z + i) * 128 + 4 * h + j) * 128 + 4 * w + k];
}

// ---------------- pe_w transpose (192x128 -> 128x192) ----------------
__global__ void transpose_pew_kernel(const float* __restrict__ pe_w)
{
    int idx = blockIdx.x * blockDim.x + threadIdx.x;
    if (idx >= 128 * C) return;
    int k = idx / C, n = idx % C;
    g_pewT[idx] = pe_w[n * 128 + k];
}

// ---------------- reconstruction scatter: (NPOS,128) -> output layout ----------------
__global__ void scatter_kernel(const float* __restrict__ rec, const float* __restrict__ rec_b,
                               float* __restrict__ out)
{
    int idx = blockIdx.x * blockDim.x + threadIdx.x;
    if (idx >= NPOS * 128) return;
    int t = idx & 127, pos = idx >> 7;
    int w = pos & 31, h = (pos >> 5) & 31, z = (pos >> 10) & 31, b = pos >> 15;
    int o = t >> 5, i = (t >> 4) & 1, j = (t >> 2) & 3, k = t & 3;
    out[((((size_t)b * 4 + o) * 64 + 2 * z + i) * 128 + 4 * h + j) * 128 + 4 * w + k]
        = rec[idx] + rec_b[o];
}

// ---------------- host launcher ----------------
extern "C" void kernel_launch(void* const* d_in, const int* in_sizes, int n_in,
                              void* d_out, int out_size)
{
    const float* x       = (const float*)d_in[0];
    const float* pe_w    = (const float*)d_in[1];
    const float* pe_b    = (const float*)d_in[2];
    const float* pe_ln_g = (const float*)d_in[3];
    const float* pe_ln_b = (const float*)d_in[4];
    const float* ln1_g   = (const float*)d_in[5];
    const float* ln1_b   = (const float*)d_in[6];
    const float* qkv_w   = (const float*)d_in[7];
    const float* qkv_b   = (const float*)d_in[8];
    const float* proj_w  = (const float*)d_in[9];
    const float* proj_b  = (const float*)d_in[10];
    const float* rpb     = (const float*)d_in[11];
    const float* ln2_g   = (const float*)d_in[12];
    const float* ln2_b   = (const float*)d_in[13];
    const float* fc1_w   = (const float*)d_in[14];
    const float* fc1_b   = (const float*)d_in[15];
    const float* fc2_w   = (const float*)d_in[16];
    const float* fc2_b   = (const float*)d_in[17];
    const float* rec_w   = (const float*)d_in[18];
    const float* rec_b   = (const float*)d_in[19];
    float* out = (float*)d_out;

    float *e, *w, *qkv, *h, *zeros;
    cudaGetSymbolAddress((void**)&e,    g_e);
    cudaGetSymbolAddress((void**)&w,    g_w);
    cudaGetSymbolAddress((void**)&qkv,  g_qkv);
    cudaGetSymbolAddress((void**)&h,    g_h);
    cudaGetSymbolAddress((void**)&zeros, g_zeros);

    const int ATTN_SMEM = (3 * 128 * 33 + 128 * 129) * (int)sizeof(float); // 116736
    cudaFuncSetAttribute(attn_kernel, cudaFuncAttributeMaxDynamicSharedMemorySize, ATTN_SMEM);

    // ---- patch embed: gather -> GEMM -> LN ----
    transpose_pew_kernel<<<(128 * C + 255) / 256, 256>>>(pe_w);
    gather_kernel<<<(NPOS * 128) / 256, 256>>>(x, h);
    {
        float* pewT; cudaGetSymbolAddress((void**)&pewT, g_pewT);
        gemm_kernel<0, 0><<<dim3(C / 64, NPOS / 64), 256>>>(h, pewT, pe_b, w, NPOS, C, 128);
    }
    ln_kernel<<<NPOS, 192>>>(w, e, pe_ln_g, pe_ln_b, 0);

    // ---- transformer layers ----
    for (int d = 0; d < DEPTH; d++) {
        int sh = d & 1;
        // LN1 + shift + window partition
        ln_kernel<<<NPOS, 192>>>(e, w, ln1_g + d * C, ln1_b + d * C, sh ? 2 : 1);
        // qkv
        gemm_kernel<0, 0><<<dim3((3 * C) / 64, NPOS / 64), 256>>>(
            w, qkv_w + (size_t)d * C * 3 * C, qkv_b + d * 3 * C, qkv, NPOS, 3 * C, C);
        // attention
        attn_kernel<<<dim3(B * NW, HEADS), 256, ATTN_SMEM>>>(rpb + (size_t)d * TBL * HEADS, sh);
        // proj (into window-layout scratch)
        {
            float* o; cudaGetSymbolAddress((void**)&o, g_o);
            gemm_kernel<0, 0><<<dim3(C / 64, NPOS / 64), 256>>>(
                o, proj_w + (size_t)d * C * C, proj_b + d * C, w, NPOS, C, C);
        }
        // un-window + reverse roll + residual
        unwin_add_kernel<<<(NPOS * C) / 256, 256>>>(e, w, sh);
        // LN2
        ln_kernel<<<NPOS, 192>>>(e, w, ln2_g + d * C, ln2_b + d * C, 0);
        // fc1 + gelu
        gemm_kernel<1, 0><<<dim3((4 * C) / 64, NPOS / 64), 256>>>(
            w, fc1_w + (size_t)d * C * 4 * C, fc1_b + d * 4 * C, h, NPOS, 4 * C, C);
        // fc2 (+= residual)
        gemm_kernel<0, 1><<<dim3(C / 64, NPOS / 64), 256>>>(
            h, fc2_w + (size_t)d * 4 * C * C, fc2_b + d * C, e, NPOS, C, 4 * C);
    }

    // ---- reconstruction: GEMM -> scatter ----
    gemm_kernel<0, 0><<<dim3(128 / 64, NPOS / 64), 256>>>(e, rec_w, zeros, qkv, NPOS, 128, C);
    scatter_kernel<<<(NPOS * 128) / 256, 256>>>(qkv, rec_b, out);
}

// round 2
// speedup vs baseline: 1.8385x; 1.8385x over previous
#include <cuda_runtime.h>
#include <math.h>

typedef unsigned long long ull;

// ---------------- problem constants ----------------
#define B 2
#define C 192
#define HEADS 6
#define ZP 32
#define NPOS (B*ZP*ZP*ZP)          // 65536 token positions
#define NW 256                      // windows per batch
#define DEPTH 4
#define TBL 675

// ---------------- scratch ----------------
__device__ float g_e  [(size_t)NPOS * C];
__device__ float g_w  [(size_t)NPOS * C];
__device__ float g_qkv[(size_t)NPOS * 3 * C];
__device__ float g_o  [(size_t)NPOS * C];
__device__ float g_h  [(size_t)NPOS * 4 * C];
__device__ float g_pewT[128 * C];
__device__ float g_zeros[128];

// ---------------- f32x2 helpers ----------------
__device__ __forceinline__ void fma2(ull &d, ull a, ull b){
    asm("fma.rn.f32x2 %0, %1, %2, %0;" : "+l"(d) : "l"(a), "l"(b));
}
__device__ __forceinline__ ull dup2(float x){
    ull r; asm("mov.b64 %0, {%1, %1};" : "=l"(r) : "f"(x)); return r;
}
__device__ __forceinline__ float2 unpack2(ull v){
    float2 f; asm("mov.b64 {%0, %1}, %2;" : "=f"(f.x), "=f"(f.y) : "l"(v)); return f;
}
__device__ __forceinline__ float gelu_f(float v){
    return 0.5f * v * (1.0f + erff(v * 0.70710678118654752f));
}

// ---------------- f32x2 tiled GEMM: 128x128x16, 8x8 per thread ----------------
template<int ACT, int BETA>
__global__ __launch_bounds__(256, 2)
void gemm2_kernel(const float* __restrict__ A, const float* __restrict__ Bm,
                  const float* __restrict__ bias, float* __restrict__ Cm,
                  int M, int N, int K)
{
    __shared__ float As[2][16][132];
    __shared__ float Bs[2][16][128];
    const int bm = blockIdx.y << 7;
    const int bn = blockIdx.x << 7;
    const int t  = threadIdx.x;
    const int tx = t & 15, ty = t >> 4;
    const int K4 = K >> 2, N4 = N >> 2;

    const float4* A4 = (const float4*)A;
    const float4* B4 = (const float4*)Bm;
    const int ar = t >> 2, aq = t & 3;
    const int bkr = t >> 5, bnc = t & 31;
    const size_t aoff  = (size_t)(bm + ar) * K4 + aq;
    const size_t aoff2 = aoff + (size_t)64 * K4;
    const size_t boff  = (size_t)bkr * N4 + (bn >> 2) + bnc;
    const size_t boff2 = boff + (size_t)8 * N4;
    const bool bvalid = (bn + bnc * 4) < N;
    const float4 z4 = make_float4(0.f, 0.f, 0.f, 0.f);

    const int nk = K >> 4;
    float4 a0 = A4[aoff], a1 = A4[aoff2];
    float4 b0 = bvalid ? B4[boff]  : z4;
    float4 b1 = bvalid ? B4[boff2] : z4;
    As[0][4*aq+0][ar]    = a0.x; As[0][4*aq+1][ar]    = a0.y;
    As[0][4*aq+2][ar]    = a0.z; As[0][4*aq+3][ar]    = a0.w;
    As[0][4*aq+0][64+ar] = a1.x; As[0][4*aq+1][64+ar] = a1.y;
    As[0][4*aq+2][64+ar] = a1.z; As[0][4*aq+3][64+ar] = a1.w;
    *(float4*)&Bs[0][bkr][bnc*4]   = b0;
    *(float4*)&Bs[0][8+bkr][bnc*4] = b1;
    __syncthreads();

    ull acc[4][8];
#pragma unroll
    for (int p = 0; p < 4; p++)
#pragma unroll
        for (int c = 0; c < 8; c++) acc[p][c] = 0ull;

    for (int kt = 0; kt < nk; kt++) {
        const int buf = kt & 1;
        if (kt + 1 < nk) {
            size_t ka = (size_t)(kt + 1) * 4;
            size_t kb = (size_t)(kt + 1) * 16 * N4;
            a0 = A4[aoff + ka]; a1 = A4[aoff2 + ka];
            b0 = bvalid ? B4[boff + kb]  : z4;
            b1 = bvalid ? B4[boff2 + kb] : z4;
        }
#pragma unroll
        for (int kk = 0; kk < 16; kk++) {
            ulonglong2 ap01 = *(const ulonglong2*)&As[buf][kk][ty*4];
            ulonglong2 ap23 = *(const ulonglong2*)&As[buf][kk][64+ty*4];
            float4 bv0 = *(const float4*)&Bs[buf][kk][tx*4];
            float4 bv1 = *(const float4*)&Bs[buf][kk][64+tx*4];
            ull ap[4] = {ap01.x, ap01.y, ap23.x, ap23.y};
            float bf[8] = {bv0.x, bv0.y, bv0.z, bv0.w, bv1.x, bv1.y, bv1.z, bv1.w};
#pragma unroll
            for (int c = 0; c < 8; c++) {
                ull bd = dup2(bf[c]);
#pragma unroll
                for (int p = 0; p < 4; p++) fma2(acc[p][c], ap[p], bd);
            }
        }
        if (kt + 1 < nk) {
            const int nb = buf ^ 1;
            As[nb][4*aq+0][ar]    = a0.x; As[nb][4*aq+1][ar]    = a0.y;
            As[nb][4*aq+2][ar]    = a0.z; As[nb][4*aq+3][ar]    = a0.w;
            As[nb][4*aq+0][64+ar] = a1.x; As[nb][4*aq+1][64+ar] = a1.y;
            As[nb][4*aq+2][64+ar] = a1.z; As[nb][4*aq+3][64+ar] = a1.w;
            *(float4*)&Bs[nb][bkr][bnc*4]   = b0;
            *(float4*)&Bs[nb][8+bkr][bnc*4] = b1;
        }
        __syncthreads();
    }

    // epilogue
    float cf[8][8];
#pragma unroll
    for (int p = 0; p < 4; p++) {
        int rr = 2 * p;
#pragma unroll
        for (int c = 0; c < 8; c++) {
            float2 v = unpack2(acc[p][c]);
            cf[rr][c] = v.x; cf[rr+1][c] = v.y;
        }
    }
    const bool g1v = (bn + 64) < N;
    float4 bias0 = *(const float4*)&bias[bn + tx*4];
    float4 bias1 = g1v ? *(const float4*)&bias[bn + 64 + tx*4] : z4;
#pragma unroll
    for (int i = 0; i < 8; i++) {
        int row = bm + (i < 4 ? ty*4 + i : 64 + ty*4 + i - 4);
        float4 v0 = make_float4(cf[i][0]+bias0.x, cf[i][1]+bias0.y,
                                cf[i][2]+bias0.z, cf[i][3]+bias0.w);
        if (ACT) { v0.x = gelu_f(v0.x); v0.y = gelu_f(v0.y); v0.z = gelu_f(v0.z); v0.w = gelu_f(v0.w); }
        size_t o0 = (size_t)row * N + bn + tx*4;
        if (BETA) {
            float4 old = *(const float4*)&Cm[o0];
            v0.x += old.x; v0.y += old.y; v0.z += old.z; v0.w += old.w;
        }
        *(float4*)&Cm[o0] = v0;
        if (g1v) {
            float4 v1 = make_float4(cf[i][4]+bias1.x, cf[i][5]+bias1.y,
                                    cf[i][6]+bias1.z, cf[i][7]+bias1.w);
            if (ACT) { v1.x = gelu_f(v1.x); v1.y = gelu_f(v1.y); v1.z = gelu_f(v1.z); v1.w = gelu_f(v1.w); }
            size_t o1 = o0 + 64;
            if (BETA) {
                float4 old = *(const float4*)&Cm[o1];
                v1.x += old.x; v1.y += old.y; v1.z += old.z; v1.w += old.w;
            }
            *(float4*)&Cm[o1] = v1;
        }
    }
}

// ---------------- warp-per-token LayerNorm ----------------
// mode: 0 flat, 1 window partition, 2 window partition + roll
__global__ __launch_bounds__(256)
void ln2_kernel(const float* __restrict__ src, float* __restrict__ dst,
                const float* __restrict__ g, const float* __restrict__ b, int mode)
{
    const int lane = threadIdx.x & 31;
    const int tok = blockIdx.x * 8 + (threadIdx.x >> 5);
    int spos;
    if (mode == 0) {
        spos = tok;
    } else {
        int n = tok & 127, wi = (tok >> 7) & 255, bb = tok >> 15;
        int zw = wi >> 4, hw = (wi >> 2) & 3, ww = wi & 3;
        int z = zw * 2 + (n >> 6), h = hw * 8 + ((n >> 3) & 7), w = ww * 8 + (n & 7);
        if (mode == 2) { z = (z + 1) & 31; h = (h + 4) & 31; w = (w + 4) & 31; }
        spos = ((bb * 32 + z) * 32 + h) * 32 + w;
    }
    const float* sp = src + (size_t)spos * C;
    float v[6]; float s = 0.f, s2 = 0.f;
#pragma unroll
    for (int j = 0; j < 6; j++) { v[j] = sp[lane + 32*j]; s += v[j]; s2 += v[j]*v[j]; }
#pragma unroll
    for (int o = 16; o > 0; o >>= 1) {
        s  += __shfl_xor_sync(0xffffffffu, s,  o);
        s2 += __shfl_xor_sync(0xffffffffu, s2, o);
    }
    float m = s * (1.0f/192.0f);
    float rstd = rsqrtf(s2 * (1.0f/192.0f) - m*m + 1e-5f);
    float* dp = dst + (size_t)tok * C;
#pragma unroll
    for (int j = 0; j < 6; j++) {
        int c = lane + 32*j;
        dp[c] = (v[j] - m) * rstd * g[c] + b[c];
    }
}

// ---------------- register-tiled window attention ----------------
// smem layout (floats): Qt[32][132], Kt[32][132], Vs[128][36], Ss[128][132], rpb[676], rid[128]
#define OQ 0
#define OK_ 4224
#define OV 8448
#define OS 13056
#define ORP 29952
#define ORID 30628
#define ATTN_SMEM_F 30756

__global__ __launch_bounds__(256)
void attn2_kernel(const float* __restrict__ rpb, int shifted)
{
    extern __shared__ float sm[];
    float* Qt = sm + OQ;
    float* Kt = sm + OK_;
    float* Vs = sm + OV;
    float* Ss = sm + OS;
    float* rpb_s = sm + ORP;
    int* rid_s = (int*)(sm + ORID);

    const int win = blockIdx.x;
    const int hh  = blockIdx.y;
    const int t = threadIdx.x;
    const int tx = t & 15, ty = t >> 4;
    const float scale = 0.1767766952966369f;

    for (int e = t; e < 4096; e += 256) {
        int n = e >> 5, d = e & 31;
        size_t base = ((size_t)(win * 128 + n)) * (3 * C) + hh * 32 + d;
        Qt[d * 132 + n] = g_qkv[base] * scale;
        Kt[d * 132 + n] = g_qkv[base + C];
        Vs[n * 36 + d]  = g_qkv[base + 2 * C];
    }
    for (int e = t; e < TBL; e += 256) rpb_s[e] = rpb[e * HEADS + hh];
    int wloc = win & 255;
    int zw = wloc >> 4, hw = (wloc >> 2) & 3, ww = wloc & 3;
    if (shifted && t < 128) {
        int z = zw * 2 + (t >> 6), h = hw * 8 + ((t >> 3) & 7), w = ww * 8 + (t & 7);
        rid_s[t] = (z < 30 ? 0 : (z < 31 ? 1 : 2)) * 9
                 + (h < 24 ? 0 : (h < 28 ? 1 : 2)) * 3
                 + (w < 24 ? 0 : (w < 28 ? 1 : 2));
    }
    __syncthreads();

    // ---- QK^T: S[n][m] ----
    ull acc[8][4];
#pragma unroll
    for (int r = 0; r < 8; r++)
#pragma unroll
        for (int j = 0; j < 4; j++) acc[r][j] = 0ull;
#pragma unroll 4
    for (int d = 0; d < 32; d++) {
        float4 q0 = *(const float4*)&Qt[d*132 + ty*4];
        float4 q1 = *(const float4*)&Qt[d*132 + 64 + ty*4];
        ulonglong2 k01 = *(const ulonglong2*)&Kt[d*132 + tx*4];
        ulonglong2 k23 = *(const ulonglong2*)&Kt[d*132 + 64 + tx*4];
        ull kp[4] = {k01.x, k01.y, k23.x, k23.y};
        float qf[8] = {q0.x, q0.y, q0.z, q0.w, q1.x, q1.y, q1.z, q1.w};
#pragma unroll
        for (int r = 0; r < 8; r++) {
            ull qd = dup2(qf[r]);
#pragma unroll
            for (int j = 0; j < 4; j++) fma2(acc[r][j], qd, kp[j]);
        }
    }
    // bias + mask + store S
#pragma unroll
    for (int rr = 0; rr < 8; rr++) {
        int n = (rr < 4 ? ty*4 + rr : 64 + ty*4 + rr - 4);
        int zn = n >> 6, hn = (n >> 3) & 7, wn = n & 7;
        int ridn = shifted ? rid_s[n] : 0;
#pragma unroll
        for (int j = 0; j < 4; j++) {
            float2 v = unpack2(acc[rr][j]);
            int mb = (j < 2 ? tx*4 + 2*j : 64 + tx*4 + 2*(j - 2));
            {
                int m = mb;
                int zm = m >> 6, hm = (m >> 3) & 7, wm = m & 7;
                int idx = (zn - zm + 1) * 225 + (hn - hm + 7) * 15 + (wn - wm + 7);
                v.x += rpb_s[idx];
                if (shifted && rid_s[m] != ridn) v.x -= 100.0f;
            }
            {
                int m = mb + 1;
                int zm = m >> 6, hm = (m >> 3) & 7, wm = m & 7;
                int idx = (zn - zm + 1) * 225 + (hn - hm + 7) * 15 + (wn - wm + 7);
                v.y += rpb_s[idx];
                if (shifted && rid_s[m] != ridn) v.y -= 100.0f;
            }
            *(float2*)&Ss[n * 132 + mb] = v;
        }
    }
    __syncthreads();

    // ---- softmax: 2 threads per row ----
    {
        int n = t >> 1, half = t & 1;
        float* row = &Ss[n * 132 + half * 64];
        float mx = -1e30f;
#pragma unroll
        for (int j = 0; j < 16; j++) {
            float4 v = *(const float4*)&row[j * 4];
            mx = fmaxf(mx, fmaxf(fmaxf(v.x, v.y), fmaxf(v.z, v.w)));
        }
        mx = fmaxf(mx, __shfl_xor_sync(0xffffffffu, mx, 1));
        float sum = 0.f;
#pragma unroll
        for (int j = 0; j < 16; j++) {
            float4 v = *(float4*)&row[j * 4];
            v.x = __expf(v.x - mx); v.y = __expf(v.y - mx);
            v.z = __expf(v.z - mx); v.w = __expf(v.w - mx);
            sum += v.x + v.y + v.z + v.w;
            *(float4*)&row[j * 4] = v;
        }
        sum += __shfl_xor_sync(0xffffffffu, sum, 1);
        float inv = 1.0f / sum;
#pragma unroll
        for (int j = 0; j < 16; j++) {
            float4 v = *(float4*)&row[j * 4];
            v.x *= inv; v.y *= inv; v.z *= inv; v.w *= inv;
            *(float4*)&row[j * 4] = v;
        }
    }
    __syncthreads();

    // ---- A @ V: 2 rows x 8 cols per thread, pairs along d ----
    {
        int r0 = (t >> 2) * 2;
        int d0 = (t & 3) * 8;
        ull av[2][4];
#pragma unroll
        for (int i = 0; i < 2; i++)
#pragma unroll
            for (int j = 0; j < 4; j++) av[i][j] = 0ull;
#pragma unroll 8
        for (int m = 0; m < 128; m++) {
            float s0 = Ss[r0 * 132 + m];
            float s1 = Ss[(r0 + 1) * 132 + m];
            ulonglong2 v01 = *(const ulonglong2*)&Vs[m * 36 + d0];
            ulonglong2 v23 = *(const ulonglong2*)&Vs[m * 36 + d0 + 4];
            ull sd0 = dup2(s0), sd1 = dup2(s1);
            fma2(av[0][0], sd0, v01.x); fma2(av[0][1], sd0, v01.y);
            fma2(av[0][2], sd0, v23.x); fma2(av[0][3], sd0, v23.y);
            fma2(av[1][0], sd1, v01.x); fma2(av[1][1], sd1, v01.y);
            fma2(av[1][2], sd1, v23.x); fma2(av[1][3], sd1, v23.y);
        }
#pragma unroll
        for (int i = 0; i < 2; i++) {
            float of[8];
#pragma unroll
            for (int j = 0; j < 4; j++) {
                float2 v = unpack2(av[i][j]);
                of[2*j] = v.x; of[2*j+1] = v.y;
            }
            size_t ob = ((size_t)(win * 128 + r0 + i)) * C + hh * 32 + d0;
            *(float4*)&g_o[ob]     = make_float4(of[0], of[1], of[2], of[3]);
            *(float4*)&g_o[ob + 4] = make_float4(of[4], of[5], of[6], of[7]);
        }
    }
}

// ---------------- window-merge + reverse roll + residual add ----------------
__global__ void unwin_add_kernel(float* __restrict__ e, const float* __restrict__ w, int shifted)
{
    int idx = blockIdx.x * blockDim.x + threadIdx.x;
    if (idx >= NPOS * C) return;
    int c = idx % C;
    int pos = idx / C;
    int ww2 = pos & 31, hh = (pos >> 5) & 31, z = (pos >> 10) & 31, b = pos >> 15;
    int sz = shifted ? 1 : 0, s2 = shifted ? 4 : 0;
    int z2 = (z - sz) & 31, h2 = (hh - s2) & 31, w2 = (ww2 - s2) & 31;
    int wi = ((z2 >> 1) << 4) | ((h2 >> 3) << 2) | (w2 >> 3);
    int n  = ((z2 & 1) << 6) | ((h2 & 7) << 3) | (w2 & 7);
    int tok = (b * 256 + wi) * 128 + n;
    e[idx] += w[(size_t)tok * C + c];
}

// ---------------- patch-embed gather ----------------
__global__ void gather_kernel(const float* __restrict__ x, float* __restrict__ xg)
{
    int idx = blockIdx.x * blockDim.x + threadIdx.x;
    if (idx >= NPOS * 128) return;
    int t = idx & 127, pos = idx >> 7;
    int w = pos & 31, h = (pos >> 5) & 31, z = (pos >> 10) & 31, b = pos >> 15;
    int c4 = t >> 5, i = (t >> 4) & 1, j = (t >> 2) & 3, k = t & 3;
    xg[idx] = x[((((size_t)b * 4 + c4) * 64 + 2 * z + i) * 128 + 4 * h + j) * 128 + 4 * w + k];
}

__global__ void transpose_pew_kernel(const float* __restrict__ pe_w)
{
    int idx = blockIdx.x * blockDim.x + threadIdx.x;
    if (idx >= 128 * C) return;
    int k = idx / C, n = idx % C;
    g_pewT[idx] = pe_w[n * 128 + k];
}

__global__ void scatter_kernel(const float* __restrict__ rec, const float* __restrict__ rec_b,
                               float* __restrict__ out)
{
    int idx = blockIdx.x * blockDim.x + threadIdx.x;
    if (idx >= NPOS * 128) return;
    int t = idx & 127, pos = idx >> 7;
    int w = pos & 31, h = (pos >> 5) & 31, z = (pos >> 10) & 31, b = pos >> 15;
    int o = t >> 5, i = (t >> 4) & 1, j = (t >> 2) & 3, k = t & 3;
    out[((((size_t)b * 4 + o) * 64 + 2 * z + i) * 128 + 4 * h + j) * 128 + 4 * w + k]
        = rec[idx] + rec_b[o];
}

// ---------------- host launcher ----------------
extern "C" void kernel_launch(void* const* d_in, const int* in_sizes, int n_in,
                              void* d_out, int out_size)
{
    const float* x       = (const float*)d_in[0];
    const float* pe_w    = (const float*)d_in[1];
    const float* pe_b    = (const float*)d_in[2];
    const float* pe_ln_g = (const float*)d_in[3];
    const float* pe_ln_b = (const float*)d_in[4];
    const float* ln1_g   = (const float*)d_in[5];
    const float* ln1_b   = (const float*)d_in[6];
    const float* qkv_w   = (const float*)d_in[7];
    const float* qkv_b   = (const float*)d_in[8];
    const float* proj_w  = (const float*)d_in[9];
    const float* proj_b  = (const float*)d_in[10];
    const float* rpb     = (const float*)d_in[11];
    const float* ln2_g   = (const float*)d_in[12];
    const float* ln2_b   = (const float*)d_in[13];
    const float* fc1_w   = (const float*)d_in[14];
    const float* fc1_b   = (const float*)d_in[15];
    const float* fc2_w   = (const float*)d_in[16];
    const float* fc2_b   = (const float*)d_in[17];
    const float* rec_w   = (const float*)d_in[18];
    const float* rec_b   = (const float*)d_in[19];
    float* out = (float*)d_out;

    float *e, *w, *qkv, *h, *o, *zeros, *pewT;
    cudaGetSymbolAddress((void**)&e,     g_e);
    cudaGetSymbolAddress((void**)&w,     g_w);
    cudaGetSymbolAddress((void**)&qkv,   g_qkv);
    cudaGetSymbolAddress((void**)&h,     g_h);
    cudaGetSymbolAddress((void**)&o,     g_o);
    cudaGetSymbolAddress((void**)&zeros, g_zeros);
    cudaGetSymbolAddress((void**)&pewT,  g_pewT);

    const int ATTN_SMEM = ATTN_SMEM_F * (int)sizeof(float);
    cudaFuncSetAttribute(attn2_kernel, cudaFuncAttributeMaxDynamicSharedMemorySize, ATTN_SMEM);

    // ---- patch embed: gather -> GEMM -> LN ----
    transpose_pew_kernel<<<(128 * C + 255) / 256, 256>>>(pe_w);
    gather_kernel<<<(NPOS * 128) / 256, 256>>>(x, h);
    gemm2_kernel<0, 0><<<dim3((C + 127) / 128, NPOS / 128), 256>>>(h, pewT, pe_b, w, NPOS, C, 128);
    ln2_kernel<<<NPOS / 8, 256>>>(w, e, pe_ln_g, pe_ln_b, 0);

    // ---- transformer layers ----
    for (int d = 0; d < DEPTH; d++) {
        int sh = d & 1;
        ln2_kernel<<<NPOS / 8, 256>>>(e, w, ln1_g + d * C, ln1_b + d * C, sh ? 2 : 1);
        gemm2_kernel<0, 0><<<dim3((3 * C + 127) / 128, NPOS / 128), 256>>>(
            w, qkv_w + (size_t)d * C * 3 * C, qkv_b + d * 3 * C, qkv, NPOS, 3 * C, C);
        attn2_kernel<<<dim3(B * NW, HEADS), 256, ATTN_SMEM>>>(rpb + (size_t)d * TBL * HEADS, sh);
        gemm2_kernel<0, 0><<<dim3((C + 127) / 128, NPOS / 128), 256>>>(
            o, proj_w + (size_t)d * C * C, proj_b + d * C, w, NPOS, C, C);
        unwin_add_kernel<<<(NPOS * C) / 256, 256>>>(e, w, sh);
        ln2_kernel<<<NPOS / 8, 256>>>(e, w, ln2_g + d * C, ln2_b + d * C, 0);
        gemm2_kernel<1, 0><<<dim3((4 * C + 127) / 128, NPOS / 128), 256>>>(
            w, fc1_w + (size_t)d * C * 4 * C, fc1_b + d * 4 * C, h, NPOS, 4 * C, C);
        gemm2_kernel<0, 1><<<dim3((C + 127) / 128, NPOS / 128), 256>>>(
            h, fc2_w + (size_t)d * 4 * C * C, fc2_b + d * C, e, NPOS, C, 4 * C);
    }

    // ---- reconstruction ----
    gemm2_kernel<0, 0><<<dim3(1, NPOS / 128), 256>>>(e, rec_w, zeros, qkv, NPOS, 128, C);
    scatter_kernel<<<(NPOS * 128) / 256, 256>>>(qkv, rec_b, out);
}

// round 6
// speedup vs baseline: 3.1168x; 1.6952x over previous
#include <cuda_runtime.h>
#include <math.h>
#include <stdint.h>

typedef unsigned long long ull;

// ---------------- problem constants ----------------
#define B 2
#define C 192
#define HEADS 6
#define ZP 32
#define NPOS (B*ZP*ZP*ZP)          // 65536
#define NW 256
#define DEPTH 4
#define TBL 675

// weight-transpose scratch offsets (floats)
#define QO 0
#define PO 442368
#define F1O 589824
#define F2O 1179648
#define RO 1769472
#define WT_TOTAL 1794048

// ---------------- scratch ----------------
__device__ float g_e  [(size_t)NPOS * C];
__device__ float g_w  [(size_t)NPOS * C];
__device__ float g_qkv[(size_t)NPOS * 3 * C];
__device__ float g_o  [(size_t)NPOS * C];
__device__ float g_h  [(size_t)NPOS * 4 * C];
__device__ float g_wt [WT_TOTAL];
__device__ float g_zeros[192];

// ---------------- helpers ----------------
__device__ __forceinline__ float gelu_f(float v){
    return 0.5f * v * (1.0f + erff(v * 0.70710678118654752f));
}
// f32x2 (attention)
__device__ __forceinline__ void fma2(ull &d, ull a, ull b){
    asm("fma.rn.f32x2 %0, %1, %2, %0;" : "+l"(d) : "l"(a), "l"(b));
}
__device__ __forceinline__ ull dup2(float x){
    ull r; asm("mov.b64 %0, {%1, %1};" : "=l"(r) : "f"(x)); return r;
}
__device__ __forceinline__ float2 unpack2(ull v){
    float2 f; asm("mov.b64 {%0, %1}, %2;" : "=f"(f.x), "=f"(f.y) : "l"(v)); return f;
}
// tf32 mma.sync (sm_80+ baseline feature — compiles at compute_103)
__device__ __forceinline__ void mma_tf32(float* d, const uint32_t* a, const uint32_t* b){
    asm volatile(
        "mma.sync.aligned.m16n8k8.row.col.f32.tf32.tf32.f32 "
        "{%0,%1,%2,%3}, {%4,%5,%6,%7}, {%8,%9}, {%0,%1,%2,%3};"
        : "+f"(d[0]), "+f"(d[1]), "+f"(d[2]), "+f"(d[3])
        : "r"(a[0]), "r"(a[1]), "r"(a[2]), "r"(a[3]), "r"(b[0]), "r"(b[1]));
}

// ================= tf32 mma.sync GEMM =================
// D[M,N] = act(A[M,K] @ Wt[N,K]^T + bias)  (+= if BETA)
// CTA tile 128x64, 8 warps (4x2), warp tile 32x32. Kc=32.
template<int ACT, int BETA>
__global__ __launch_bounds__(256)
void gemm_mma(const float* __restrict__ A, const float* __restrict__ Bw,
              const float* __restrict__ bias, float* __restrict__ Cm,
              int N, int K)
{
    __shared__ float As[128 * 36];
    __shared__ float Bs[64 * 36];
    const int t = threadIdx.x;
    const int lane = t & 31, wid = t >> 5;
    const int wr = wid >> 1, wc = wid & 1;
    const int warpM = wr * 32, warpN = wc * 32;
    const int g = lane >> 2, tg = lane & 3;
    const int bm = blockIdx.y << 7;
    const int bn = blockIdx.x << 6;
    const int K4 = K >> 2;
    const int nk = K >> 5;

    // gmem load geometry: per k-tile, A: 4 rows-of-32 x 1 float4; B: 2 x
    const float4* A4 = (const float4*)A;
    const float4* B4 = (const float4*)Bw;
    const int lrow = t >> 3;        // 0..31
    const int lk4  = t & 7;         // float4 index within 32-float chunk
    size_t aBase[4]; int aSm[4];
#pragma unroll
    for (int i = 0; i < 4; i++) {
        int row = lrow + i * 32;
        aBase[i] = (size_t)(bm + row) * K4 + lk4;
        aSm[i] = row * 36 + lk4 * 4;
    }
    size_t bBase[2]; int bSm[2];
#pragma unroll
    for (int i = 0; i < 2; i++) {
        int row = lrow + i * 32;
        bBase[i] = (size_t)(bn + row) * K4 + lk4;
        bSm[i] = row * 36 + lk4 * 4;
    }

    float4 pa[4], pb[2];
#pragma unroll
    for (int i = 0; i < 4; i++) pa[i] = A4[aBase[i]];
#pragma unroll
    for (int i = 0; i < 2; i++) pb[i] = B4[bBase[i]];

    float acc[2][4][4];
#pragma unroll
    for (int mi = 0; mi < 2; mi++)
#pragma unroll
        for (int ni = 0; ni < 4; ni++)
#pragma unroll
            for (int j = 0; j < 4; j++) acc[mi][ni][j] = 0.f;

    const uint32_t* Asu = (const uint32_t*)As;
    const uint32_t* Bsu = (const uint32_t*)Bs;

    for (int kt = 0; kt < nk; kt++) {
#pragma unroll
        for (int i = 0; i < 4; i++) *(float4*)&As[aSm[i]] = pa[i];
#pragma unroll
        for (int i = 0; i < 2; i++) *(float4*)&Bs[bSm[i]] = pb[i];
        __syncthreads();
        if (kt + 1 < nk) {
            size_t ko = (size_t)(kt + 1) * 8;
#pragma unroll
            for (int i = 0; i < 4; i++) pa[i] = A4[aBase[i] + ko];
#pragma unroll
            for (int i = 0; i < 2; i++) pb[i] = B4[bBase[i] + ko];
        }
#pragma unroll
        for (int ks = 0; ks < 4; ks++) {
            const int k0 = ks * 8;
            uint32_t af[2][4], bf[4][2];
#pragma unroll
            for (int mi = 0; mi < 2; mi++) {
                int r = (warpM + mi * 16 + g) * 36 + k0 + tg;
                af[mi][0] = Asu[r];
                af[mi][1] = Asu[r + 8 * 36];
                af[mi][2] = Asu[r + 4];
                af[mi][3] = Asu[r + 8 * 36 + 4];
            }
#pragma unroll
            for (int ni = 0; ni < 4; ni++) {
                int r = (warpN + ni * 8 + g) * 36 + k0 + tg;
                bf[ni][0] = Bsu[r];
                bf[ni][1] = Bsu[r + 4];
            }
#pragma unroll
            for (int mi = 0; mi < 2; mi++)
#pragma unroll
                for (int ni = 0; ni < 4; ni++)
                    mma_tf32(acc[mi][ni], af[mi], bf[ni]);
        }
        __syncthreads();
    }

    // epilogue: direct float2 stores (32B-sector coalesced)
#pragma unroll
    for (int mi = 0; mi < 2; mi++) {
        int r0 = bm + warpM + mi * 16 + g;
#pragma unroll
        for (int ni = 0; ni < 4; ni++) {
            int cb = bn + warpN + ni * 8 + 2 * tg;
            float b0 = bias[cb], b1 = bias[cb + 1];
            float v0 = acc[mi][ni][0] + b0, v1 = acc[mi][ni][1] + b1;
            float v2 = acc[mi][ni][2] + b0, v3 = acc[mi][ni][3] + b1;
            if (ACT) { v0 = gelu_f(v0); v1 = gelu_f(v1); v2 = gelu_f(v2); v3 = gelu_f(v3); }
            size_t o0 = (size_t)r0 * N + cb;
            size_t o1 = (size_t)(r0 + 8) * N + cb;
            if (BETA) {
                float2 x0 = *(const float2*)&Cm[o0];
                float2 x1 = *(const float2*)&Cm[o1];
                v0 += x0.x; v1 += x0.y; v2 += x1.x; v3 += x1.y;
            }
            *(float2*)&Cm[o0] = make_float2(v0, v1);
            *(float2*)&Cm[o1] = make_float2(v2, v3);
        }
    }
}

// ---------------- weight transpose: [K,N] -> [N,K] ----------------
__global__ void transpose_w(const float* __restrict__ src, float* __restrict__ dst,
                            int K, int N)
{
    int idx = blockIdx.x * blockDim.x + threadIdx.x;
    if (idx >= K * N) return;
    int k = idx / N, n = idx % N;
    dst[(size_t)n * K + k] = src[idx];
}

// ---------------- warp-per-token LayerNorm ----------------
// mode: 0 flat, 1 window partition, 2 window partition + roll
__global__ __launch_bounds__(256)
void ln2_kernel(const float* __restrict__ src, float* __restrict__ dst,
                const float* __restrict__ g, const float* __restrict__ b, int mode)
{
    const int lane = threadIdx.x & 31;
    const int tok = blockIdx.x * 8 + (threadIdx.x >> 5);
    int spos;
    if (mode == 0) {
        spos = tok;
    } else {
        int n = tok & 127, wi = (tok >> 7) & 255, bb = tok >> 15;
        int zw = wi >> 4, hw = (wi >> 2) & 3, ww = wi & 3;
        int z = zw * 2 + (n >> 6), h = hw * 8 + ((n >> 3) & 7), w = ww * 8 + (n & 7);
        if (mode == 2) { z = (z + 1) & 31; h = (h + 4) & 31; w = (w + 4) & 31; }
        spos = ((bb * 32 + z) * 32 + h) * 32 + w;
    }
    const float* sp = src + (size_t)spos * C;
    float v[6]; float s = 0.f, s2 = 0.f;
#pragma unroll
    for (int j = 0; j < 6; j++) { v[j] = sp[lane + 32*j]; s += v[j]; s2 += v[j]*v[j]; }
#pragma unroll
    for (int o = 16; o > 0; o >>= 1) {
        s  += __shfl_xor_sync(0xffffffffu, s,  o);
        s2 += __shfl_xor_sync(0xffffffffu, s2, o);
    }
    float m = s * (1.0f/192.0f);
    float rstd = rsqrtf(s2 * (1.0f/192.0f) - m*m + 1e-5f);
    float* dp = dst + (size_t)tok * C;
#pragma unroll
    for (int j = 0; j < 6; j++) {
        int c = lane + 32*j;
        dp[c] = (v[j] - m) * rstd * g[c] + b[c];
    }
}

// ---------------- fused window-merge + residual add + LayerNorm ----------------
__global__ __launch_bounds__(256)
void lnfuse_kernel(float* __restrict__ e, const float* __restrict__ wwin,
                   float* __restrict__ dst,
                   const float* __restrict__ g, const float* __restrict__ b, int shifted)
{
    const int lane = threadIdx.x & 31;
    const int pos = blockIdx.x * 8 + (threadIdx.x >> 5);
    int ww2 = pos & 31, hh = (pos >> 5) & 31, z = (pos >> 10) & 31, bb = pos >> 15;
    int sz = shifted ? 1 : 0, s4 = shifted ? 4 : 0;
    int z2 = (z - sz) & 31, h2 = (hh - s4) & 31, w2 = (ww2 - s4) & 31;
    int wi = ((z2 >> 1) << 4) | ((h2 >> 3) << 2) | (w2 >> 3);
    int n  = ((z2 & 1) << 6) | ((h2 & 7) << 3) | (w2 & 7);
    int tok = (bb * 256 + wi) * 128 + n;

    float* ep = e + (size_t)pos * C;
    const float* wp = wwin + (size_t)tok * C;
    float v[6]; float s = 0.f, s2 = 0.f;
#pragma unroll
    for (int j = 0; j < 6; j++) {
        int c = lane + 32*j;
        float a = ep[c] + wp[c];
        ep[c] = a;
        v[j] = a; s += a; s2 += a*a;
    }
#pragma unroll
    for (int o = 16; o > 0; o >>= 1) {
        s  += __shfl_xor_sync(0xffffffffu, s,  o);
        s2 += __shfl_xor_sync(0xffffffffu, s2, o);
    }
    float m = s * (1.0f/192.0f);
    float rstd = rsqrtf(s2 * (1.0f/192.0f) - m*m + 1e-5f);
    float* dp = dst + (size_t)pos * C;
#pragma unroll
    for (int j = 0; j < 6; j++) {
        int c = lane + 32*j;
        dp[c] = (v[j] - m) * rstd * g[c] + b[c];
    }
}

// ---------------- register-tiled window attention (f32x2) ----------------
#define OQ 0
#define OK_ 4224
#define OV 8448
#define OS 13056
#define ORP 29952
#define ORID 30628
#define ATTN_SMEM_F 30756

__global__ __launch_bounds__(256)
void attn2_kernel(const float* __restrict__ rpb, int shifted)
{
    extern __shared__ float sm[];
    float* Qt = sm + OQ;
    float* Kt = sm + OK_;
    float* Vs = sm + OV;
    float* Ss = sm + OS;
    float* rpb_s = sm + ORP;
    int* rid_s = (int*)(sm + ORID);

    const int win = blockIdx.x;
    const int hh  = blockIdx.y;
    const int t = threadIdx.x;
    const int tx = t & 15, ty = t >> 4;
    const float scale = 0.1767766952966369f;

    for (int e = t; e < 4096; e += 256) {
        int n = e >> 5, d = e & 31;
        size_t base = ((size_t)(win * 128 + n)) * (3 * C) + hh * 32 + d;
        Qt[d * 132 + n] = g_qkv[base] * scale;
        Kt[d * 132 + n] = g_qkv[base + C];
        Vs[n * 36 + d]  = g_qkv[base + 2 * C];
    }
    for (int e = t; e < TBL; e += 256) rpb_s[e] = rpb[e * HEADS + hh];
    int wloc = win & 255;
    int zw = wloc >> 4, hw = (wloc >> 2) & 3, ww = wloc & 3;
    if (shifted && t < 128) {
        int z = zw * 2 + (t >> 6), h = hw * 8 + ((t >> 3) & 7), w = ww * 8 + (t & 7);
        rid_s[t] = (z < 30 ? 0 : (z < 31 ? 1 : 2)) * 9
                 + (h < 24 ? 0 : (h < 28 ? 1 : 2)) * 3
                 + (w < 24 ? 0 : (w < 28 ? 1 : 2));
    }
    __syncthreads();

    ull acc[8][4];
#pragma unroll
    for (int r = 0; r < 8; r++)
#pragma unroll
        for (int j = 0; j < 4; j++) acc[r][j] = 0ull;
#pragma unroll 4
    for (int d = 0; d < 32; d++) {
        float4 q0 = *(const float4*)&Qt[d*132 + ty*4];
        float4 q1 = *(const float4*)&Qt[d*132 + 64 + ty*4];
        ulonglong2 k01 = *(const ulonglong2*)&Kt[d*132 + tx*4];
        ulonglong2 k23 = *(const ulonglong2*)&Kt[d*132 + 64 + tx*4];
        ull kp[4] = {k01.x, k01.y, k23.x, k23.y};
        float qf[8] = {q0.x, q0.y, q0.z, q0.w, q1.x, q1.y, q1.z, q1.w};
#pragma unroll
        for (int r = 0; r < 8; r++) {
            ull qd = dup2(qf[r]);
#pragma unroll
            for (int j = 0; j < 4; j++) fma2(acc[r][j], qd, kp[j]);
        }
    }
#pragma unroll
    for (int rr = 0; rr < 8; rr++) {
        int n = (rr < 4 ? ty*4 + rr : 64 + ty*4 + rr - 4);
        int zn = n >> 6, hn = (n >> 3) & 7, wn = n & 7;
        int ridn = shifted ? rid_s[n] : 0;
#pragma unroll
        for (int j = 0; j < 4; j++) {
            float2 v = unpack2(acc[rr][j]);
            int mb = (j < 2 ? tx*4 + 2*j : 64 + tx*4 + 2*(j - 2));
            {
                int m = mb;
                int zm = m >> 6, hm = (m >> 3) & 7, wm = m & 7;
                int idx = (zn - zm + 1) * 225 + (hn - hm + 7) * 15 + (wn - wm + 7);
                v.x += rpb_s[idx];
                if (shifted && rid_s[m] != ridn) v.x -= 100.0f;
            }
            {
                int m = mb + 1;
                int zm = m >> 6, hm = (m >> 3) & 7, wm = m & 7;
                int idx = (zn - zm + 1) * 225 + (hn - hm + 7) * 15 + (wn - wm + 7);
                v.y += rpb_s[idx];
                if (shifted && rid_s[m] != ridn) v.y -= 100.0f;
            }
            *(float2*)&Ss[n * 132 + mb] = v;
        }
    }
    __syncthreads();

    {
        int n = t >> 1, half = t & 1;
        float* row = &Ss[n * 132 + half * 64];
        float mx = -1e30f;
#pragma unroll
        for (int j = 0; j < 16; j++) {
            float4 v = *(const float4*)&row[j * 4];
            mx = fmaxf(mx, fmaxf(fmaxf(v.x, v.y), fmaxf(v.z, v.w)));
        }
        mx = fmaxf(mx, __shfl_xor_sync(0xffffffffu, mx, 1));
        float sum = 0.f;
#pragma unroll
        for (int j = 0; j < 16; j++) {
            float4 v = *(float4*)&row[j * 4];
            v.x = __expf(v.x - mx); v.y = __expf(v.y - mx);
            v.z = __expf(v.z - mx); v.w = __expf(v.w - mx);
            sum += v.x + v.y + v.z + v.w;
            *(float4*)&row[j * 4] = v;
        }
        sum += __shfl_xor_sync(0xffffffffu, sum, 1);
        float inv = 1.0f / sum;
#pragma unroll
        for (int j = 0; j < 16; j++) {
            float4 v = *(float4*)&row[j * 4];
            v.x *= inv; v.y *= inv; v.z *= inv; v.w *= inv;
            *(float4*)&row[j * 4] = v;
        }
    }
    __syncthreads();

    {
        int r0 = (t >> 2) * 2;
        int d0 = (t & 3) * 8;
        ull av[2][4];
#pragma unroll
        for (int i = 0; i < 2; i++)
#pragma unroll
            for (int j = 0; j < 4; j++) av[i][j] = 0ull;
#pragma unroll 8
        for (int m = 0; m < 128; m++) {
            float s0 = Ss[r0 * 132 + m];
            float s1 = Ss[(r0 + 1) * 132 + m];
            ulonglong2 v01 = *(const ulonglong2*)&Vs[m * 36 + d0];
            ulonglong2 v23 = *(const ulonglong2*)&Vs[m * 36 + d0 + 4];
            ull sd0 = dup2(s0), sd1 = dup2(s1);
            fma2(av[0][0], sd0, v01.x); fma2(av[0][1], sd0, v01.y);
            fma2(av[0][2], sd0, v23.x); fma2(av[0][3], sd0, v23.y);
            fma2(av[1][0], sd1, v01.x); fma2(av[1][1], sd1, v01.y);
            fma2(av[1][2], sd1, v23.x); fma2(av[1][3], sd1, v23.y);
        }
#pragma unroll
        for (int i = 0; i < 2; i++) {
            float of[8];
#pragma unroll
            for (int j = 0; j < 4; j++) {
                float2 v = unpack2(av[i][j]);
                of[2*j] = v.x; of[2*j+1] = v.y;
            }
            size_t ob = ((size_t)(win * 128 + r0 + i)) * C + hh * 32 + d0;
            *(float4*)&g_o[ob]     = make_float4(of[0], of[1], of[2], of[3]);
            *(float4*)&g_o[ob + 4] = make_float4(of[4], of[5], of[6], of[7]);
        }
    }
}

// ---------------- patch-embed gather / recon scatter ----------------
__global__ void gather_kernel(const float* __restrict__ x, float* __restrict__ xg)
{
    int idx = blockIdx.x * blockDim.x + threadIdx.x;
    if (idx >= NPOS * 128) return;
    int t = idx & 127, pos = idx >> 7;
    int w = pos & 31, h = (pos >> 5) & 31, z = (pos >> 10) & 31, b = pos >> 15;
    int c4 = t >> 5, i = (t >> 4) & 1, j = (t >> 2) & 3, k = t & 3;
    xg[idx] = x[((((size_t)b * 4 + c4) * 64 + 2 * z + i) * 128 + 4 * h + j) * 128 + 4 * w + k];
}

__global__ void scatter_kernel(const float* __restrict__ rec, const float* __restrict__ rec_b,
                               float* __restrict__ out)
{
    int idx = blockIdx.x * blockDim.x + threadIdx.x;
    if (idx >= NPOS * 128) return;
    int t = idx & 127, pos = idx >> 7;
    int w = pos & 31, h = (pos >> 5) & 31, z = (pos >> 10) & 31, b = pos >> 15;
    int o = t >> 5, i = (t >> 4) & 1, j = (t >> 2) & 3, k = t & 3;
    out[((((size_t)b * 4 + o) * 64 + 2 * z + i) * 128 + 4 * h + j) * 128 + 4 * w + k]
        = rec[idx] + rec_b[o];
}

// ---------------- host launcher ----------------
extern "C" void kernel_launch(void* const* d_in, const int* in_sizes, int n_in,
                              void* d_out, int out_size)
{
    const float* x       = (const float*)d_in[0];
    const float* pe_w    = (const float*)d_in[1];
    const float* pe_b    = (const float*)d_in[2];
    const float* pe_ln_g = (const float*)d_in[3];
    const float* pe_ln_b = (const float*)d_in[4];
    const float* ln1_g   = (const float*)d_in[5];
    const float* ln1_b   = (const float*)d_in[6];
    const float* qkv_w   = (const float*)d_in[7];
    const float* qkv_b   = (const float*)d_in[8];
    const float* proj_w  = (const float*)d_in[9];
    const float* proj_b  = (const float*)d_in[10];
    const float* rpb     = (const float*)d_in[11];
    const float* ln2_g   = (const float*)d_in[12];
    const float* ln2_b   = (const float*)d_in[13];
    const float* fc1_w   = (const float*)d_in[14];
    const float* fc1_b   = (const float*)d_in[15];
    const float* fc2_w   = (const float*)d_in[16];
    const float* fc2_b   = (const float*)d_in[17];
    const float* rec_w   = (const float*)d_in[18];
    const float* rec_b   = (const float*)d_in[19];
    float* out = (float*)d_out;

    float *e, *w, *qkv, *h, *o, *wt, *zeros;
    cudaGetSymbolAddress((void**)&e,     g_e);
    cudaGetSymbolAddress((void**)&w,     g_w);
    cudaGetSymbolAddress((void**)&qkv,   g_qkv);
    cudaGetSymbolAddress((void**)&h,     g_h);
    cudaGetSymbolAddress((void**)&o,     g_o);
    cudaGetSymbolAddress((void**)&wt,    g_wt);
    cudaGetSymbolAddress((void**)&zeros, g_zeros);

    const int ATTN_SMEM = ATTN_SMEM_F * (int)sizeof(float);
    cudaFuncSetAttribute(attn2_kernel, cudaFuncAttributeMaxDynamicSharedMemorySize, ATTN_SMEM);

    // ---- weight transposes ([K,N] -> [N,K]) ----
    for (int d = 0; d < DEPTH; d++) {
        transpose_w<<<(192*576 + 255)/256, 256>>>(qkv_w + (size_t)d*192*576, wt + QO  + (size_t)d*110592, 192, 576);
        transpose_w<<<(192*192 + 255)/256, 256>>>(proj_w + (size_t)d*192*192, wt + PO  + (size_t)d*36864, 192, 192);
        transpose_w<<<(192*768 + 255)/256, 256>>>(fc1_w + (size_t)d*192*768, wt + F1O + (size_t)d*147456, 192, 768);
        transpose_w<<<(768*192 + 255)/256, 256>>>(fc2_w + (size_t)d*768*192, wt + F2O + (size_t)d*147456, 768, 192);
    }
    transpose_w<<<(192*128 + 255)/256, 256>>>(rec_w, wt + RO, 192, 128);

    // ---- patch embed: gather -> GEMM (pe_w already [N=192, K=128]) -> LN ----
    gather_kernel<<<(NPOS * 128) / 256, 256>>>(x, h);
    gemm_mma<0,0><<<dim3(3, NPOS/128), 256>>>(h, pe_w, pe_b, w, 192, 128);
    ln2_kernel<<<NPOS / 8, 256>>>(w, e, pe_ln_g, pe_ln_b, 0);

    // ---- transformer layers ----
    for (int d = 0; d < DEPTH; d++) {
        int sh = d & 1;
        ln2_kernel<<<NPOS / 8, 256>>>(e, w, ln1_g + d * C, ln1_b + d * C, sh ? 2 : 1);
        gemm_mma<0,0><<<dim3(9, NPOS/128), 256>>>(
            w, wt + QO + (size_t)d*110592, qkv_b + d * 3 * C, qkv, 3 * C, C);
        attn2_kernel<<<dim3(B * NW, HEADS), 256, ATTN_SMEM>>>(rpb + (size_t)d * TBL * HEADS, sh);
        gemm_mma<0,0><<<dim3(3, NPOS/128), 256>>>(
            o, wt + PO + (size_t)d*36864, proj_b + d * C, w, C, C);
        // fused: e += unwindow(w); qkv = LN2(e)
        lnfuse_kernel<<<NPOS / 8, 256>>>(e, w, qkv, ln2_g + d * C, ln2_b + d * C, sh);
        gemm_mma<1,0><<<dim3(12, NPOS/128), 256>>>(
            qkv, wt + F1O + (size_t)d*147456, fc1_b + d * 4 * C, h, 4 * C, C);
        gemm_mma<0,1><<<dim3(3, NPOS/128), 256>>>(
            h, wt + F2O + (size_t)d*147456, fc2_b + d * C, e, C, 4 * C);
    }

    // ---- reconstruction ----
    gemm_mma<0,0><<<dim3(2, NPOS/128), 256>>>(e, wt + RO, zeros, qkv, 128, C);
    scatter_kernel<<<(NPOS * 128) / 256, 256>>>(qkv, rec_b, out);
}

// round 7
// speedup vs baseline: 3.2247x; 1.0346x over previous
#include <cuda_runtime.h>
#include <math.h>
#include <stdint.h>

typedef unsigned long long ull;

// ---------------- problem constants ----------------
#define B 2
#define C 192
#define HEADS 6
#define ZP 32
#define NPOS (B*ZP*ZP*ZP)          // 65536
#define NW 256
#define DEPTH 4
#define TBL 675

// weight-transpose scratch offsets (floats)
#define QO 0
#define PO 442368
#define F1O 589824
#define F2O 1179648
#define RO 1769472
#define WT_TOTAL 1794048

// ---------------- scratch ----------------
__device__ float g_e  [(size_t)NPOS * C];
__device__ float g_w  [(size_t)NPOS * C];
__device__ float g_qkv[(size_t)NPOS * 3 * C];
__device__ float g_o  [(size_t)NPOS * C];
__device__ float g_h  [(size_t)NPOS * 4 * C];
__device__ float g_wt [WT_TOTAL];
__device__ float g_zeros[192];

// ---------------- helpers ----------------
__device__ __forceinline__ float gelu_f(float v){
    return 0.5f * v * (1.0f + erff(v * 0.70710678118654752f));
}
// f32x2 (attention)
__device__ __forceinline__ void fma2(ull &d, ull a, ull b){
    asm("fma.rn.f32x2 %0, %1, %2, %0;" : "+l"(d) : "l"(a), "l"(b));
}
__device__ __forceinline__ ull dup2(float x){
    ull r; asm("mov.b64 %0, {%1, %1};" : "=l"(r) : "f"(x)); return r;
}
__device__ __forceinline__ float2 unpack2(ull v){
    float2 f; asm("mov.b64 {%0, %1}, %2;" : "=f"(f.x), "=f"(f.y) : "l"(v)); return f;
}
// tf32 mma.sync (sm_80+ baseline — compiles at compute_103)
__device__ __forceinline__ void mma_tf32(float* d, const uint32_t* a, const uint32_t* b){
    asm volatile(
        "mma.sync.aligned.m16n8k8.row.col.f32.tf32.tf32.f32 "
        "{%0,%1,%2,%3}, {%4,%5,%6,%7}, {%8,%9}, {%0,%1,%2,%3};"
        : "+f"(d[0]), "+f"(d[1]), "+f"(d[2]), "+f"(d[3])
        : "r"(a[0]), "r"(a[1]), "r"(a[2]), "r"(a[3]), "r"(b[0]), "r"(b[1]));
}
// round-to-nearest tf32 (debiases the HW RZ truncation)
__device__ __forceinline__ float tf32_rna(float x){
    uint32_t r; asm("cvt.rna.tf32.f32 %0, %1;" : "=r"(r) : "f"(x));
    return __uint_as_float(r);
}
__device__ __forceinline__ float4 rna4(float4 v){
    v.x = tf32_rna(v.x); v.y = tf32_rna(v.y);
    v.z = tf32_rna(v.z); v.w = tf32_rna(v.w);
    return v;
}

// ================= tf32 mma.sync GEMM =================
// D[M,N] = act(A[M,K] @ Wt[N,K]^T + bias)  (+= if BETA)
// CTA tile 128x64, 4 warps (each 32x64 warp tile), Kc=32, double-buffered SMEM.
template<int ACT, int BETA>
__global__ __launch_bounds__(128)
void gemm_mma(const float* __restrict__ A, const float* __restrict__ Bw,
              const float* __restrict__ bias, float* __restrict__ Cm,
              int N, int K)
{
    __shared__ float As[2][128 * 36];
    __shared__ float Bs[2][64 * 36];
    const int t = threadIdx.x;
    const int lane = t & 31, wid = t >> 5;
    const int warpM = wid * 32;
    const int g = lane >> 2, tg = lane & 3;
    const int bm = blockIdx.y << 7;
    const int bn = blockIdx.x << 6;
    const int K4 = K >> 2;
    const int nk = K >> 5;

    const float4* A4 = (const float4*)A;
    const float4* B4 = (const float4*)Bw;
    const int lrow = t >> 3;        // 0..15
    const int lk4  = t & 7;
    size_t aBase[8]; int aSm[8];
#pragma unroll
    for (int i = 0; i < 8; i++) {
        int row = lrow + i * 16;
        aBase[i] = (size_t)(bm + row) * K4 + lk4;
        aSm[i] = row * 36 + lk4 * 4;
    }
    size_t bBase[4]; int bSm[4];
#pragma unroll
    for (int i = 0; i < 4; i++) {
        int row = lrow + i * 16;
        bBase[i] = (size_t)(bn + row) * K4 + lk4;
        bSm[i] = row * 36 + lk4 * 4;
    }

    float4 pa[8], pb[4];
#pragma unroll
    for (int i = 0; i < 8; i++) pa[i] = A4[aBase[i]];
#pragma unroll
    for (int i = 0; i < 4; i++) pb[i] = B4[bBase[i]];
#pragma unroll
    for (int i = 0; i < 8; i++) *(float4*)&As[0][aSm[i]] = rna4(pa[i]);
#pragma unroll
    for (int i = 0; i < 4; i++) *(float4*)&Bs[0][bSm[i]] = rna4(pb[i]);

    float acc[2][8][4];
#pragma unroll
    for (int mi = 0; mi < 2; mi++)
#pragma unroll
        for (int ni = 0; ni < 8; ni++)
#pragma unroll
            for (int j = 0; j < 4; j++) acc[mi][ni][j] = 0.f;

    for (int kt = 0; kt < nk; kt++) {
        __syncthreads();
        const int buf = kt & 1;
        const bool more = (kt + 1 < nk);
        if (more) {
            size_t ko = (size_t)(kt + 1) * 8;
#pragma unroll
            for (int i = 0; i < 8; i++) pa[i] = A4[aBase[i] + ko];
#pragma unroll
            for (int i = 0; i < 4; i++) pb[i] = B4[bBase[i] + ko];
        }
        const uint32_t* Asu = (const uint32_t*)As[buf];
        const uint32_t* Bsu = (const uint32_t*)Bs[buf];
#pragma unroll
        for (int ks = 0; ks < 4; ks++) {
            const int k0 = ks * 8;
            uint32_t af[2][4], bf[8][2];
#pragma unroll
            for (int mi = 0; mi < 2; mi++) {
                int r = (warpM + mi * 16 + g) * 36 + k0 + tg;
                af[mi][0] = Asu[r];
                af[mi][1] = Asu[r + 8 * 36];
                af[mi][2] = Asu[r + 4];
                af[mi][3] = Asu[r + 8 * 36 + 4];
            }
#pragma unroll
            for (int ni = 0; ni < 8; ni++) {
                int r = (ni * 8 + g) * 36 + k0 + tg;
                bf[ni][0] = Bsu[r];
                bf[ni][1] = Bsu[r + 4];
            }
#pragma unroll
            for (int mi = 0; mi < 2; mi++)
#pragma unroll
                for (int ni = 0; ni < 8; ni++)
                    mma_tf32(acc[mi][ni], af[mi], bf[ni]);
        }
        if (more) {
            const int nb = buf ^ 1;
#pragma unroll
            for (int i = 0; i < 8; i++) *(float4*)&As[nb][aSm[i]] = rna4(pa[i]);
#pragma unroll
            for (int i = 0; i < 4; i++) *(float4*)&Bs[nb][bSm[i]] = rna4(pb[i]);
        }
    }

    // epilogue: direct float2 stores
#pragma unroll
    for (int mi = 0; mi < 2; mi++) {
        int r0 = bm + warpM + mi * 16 + g;
#pragma unroll
        for (int ni = 0; ni < 8; ni++) {
            int cb = bn + ni * 8 + 2 * tg;
            float b0 = bias[cb], b1 = bias[cb + 1];
            float v0 = acc[mi][ni][0] + b0, v1 = acc[mi][ni][1] + b1;
            float v2 = acc[mi][ni][2] + b0, v3 = acc[mi][ni][3] + b1;
            if (ACT) { v0 = gelu_f(v0); v1 = gelu_f(v1); v2 = gelu_f(v2); v3 = gelu_f(v3); }
            size_t o0 = (size_t)r0 * N + cb;
            size_t o1 = (size_t)(r0 + 8) * N + cb;
            if (BETA) {
                float2 x0 = *(const float2*)&Cm[o0];
                float2 x1 = *(const float2*)&Cm[o1];
                v0 += x0.x; v1 += x0.y; v2 += x1.x; v3 += x1.y;
            }
            *(float2*)&Cm[o0] = make_float2(v0, v1);
            *(float2*)&Cm[o1] = make_float2(v2, v3);
        }
    }
}

// ---------------- weight transpose: [K,N] -> [N,K] ----------------
__global__ void transpose_w(const float* __restrict__ src, float* __restrict__ dst,
                            int K, int N)
{
    int idx = blockIdx.x * blockDim.x + threadIdx.x;
    if (idx >= K * N) return;
    int k = idx / N, n = idx % N;
    dst[(size_t)n * K + k] = src[idx];
}

// ---------------- warp-per-token LayerNorm ----------------
// mode: 0 flat, 1 window partition, 2 window partition + roll
__global__ __launch_bounds__(256)
void ln2_kernel(const float* __restrict__ src, float* __restrict__ dst,
                const float* __restrict__ g, const float* __restrict__ b, int mode)
{
    const int lane = threadIdx.x & 31;
    const int tok = blockIdx.x * 8 + (threadIdx.x >> 5);
    int spos;
    if (mode == 0) {
        spos = tok;
    } else {
        int n = tok & 127, wi = (tok >> 7) & 255, bb = tok >> 15;
        int zw = wi >> 4, hw = (wi >> 2) & 3, ww = wi & 3;
        int z = zw * 2 + (n >> 6), h = hw * 8 + ((n >> 3) & 7), w = ww * 8 + (n & 7);
        if (mode == 2) { z = (z + 1) & 31; h = (h + 4) & 31; w = (w + 4) & 31; }
        spos = ((bb * 32 + z) * 32 + h) * 32 + w;
    }
    const float* sp = src + (size_t)spos * C;
    float v[6]; float s = 0.f, s2 = 0.f;
#pragma unroll
    for (int j = 0; j < 6; j++) { v[j] = sp[lane + 32*j]; s += v[j]; s2 += v[j]*v[j]; }
#pragma unroll
    for (int o = 16; o > 0; o >>= 1) {
        s  += __shfl_xor_sync(0xffffffffu, s,  o);
        s2 += __shfl_xor_sync(0xffffffffu, s2, o);
    }
    float m = s * (1.0f/192.0f);
    float rstd = rsqrtf(s2 * (1.0f/192.0f) - m*m + 1e-5f);
    float* dp = dst + (size_t)tok * C;
#pragma unroll
    for (int j = 0; j < 6; j++) {
        int c = lane + 32*j;
        dp[c] = (v[j] - m) * rstd * g[c] + b[c];
    }
}

// ---------------- fused window-merge + residual add + LayerNorm ----------------
__global__ __launch_bounds__(256)
void lnfuse_kernel(float* __restrict__ e, const float* __restrict__ wwin,
                   float* __restrict__ dst,
                   const float* __restrict__ g, const float* __restrict__ b, int shifted)
{
    const int lane = threadIdx.x & 31;
    const int pos = blockIdx.x * 8 + (threadIdx.x >> 5);
    int ww2 = pos & 31, hh = (pos >> 5) & 31, z = (pos >> 10) & 31, bb = pos >> 15;
    int sz = shifted ? 1 : 0, s4 = shifted ? 4 : 0;
    int z2 = (z - sz) & 31, h2 = (hh - s4) & 31, w2 = (ww2 - s4) & 31;
    int wi = ((z2 >> 1) << 4) | ((h2 >> 3) << 2) | (w2 >> 3);
    int n  = ((z2 & 1) << 6) | ((h2 & 7) << 3) | (w2 & 7);
    int tok = (bb * 256 + wi) * 128 + n;

    float* ep = e + (size_t)pos * C;
    const float* wp = wwin + (size_t)tok * C;
    float v[6]; float s = 0.f, s2 = 0.f;
#pragma unroll
    for (int j = 0; j < 6; j++) {
        int c = lane + 32*j;
        float a = ep[c] + wp[c];
        ep[c] = a;
        v[j] = a; s += a; s2 += a*a;
    }
#pragma unroll
    for (int o = 16; o > 0; o >>= 1) {
        s  += __shfl_xor_sync(0xffffffffu, s,  o);
        s2 += __shfl_xor_sync(0xffffffffu, s2, o);
    }
    float m = s * (1.0f/192.0f);
    float rstd = rsqrtf(s2 * (1.0f/192.0f) - m*m + 1e-5f);
    float* dp = dst + (size_t)pos * C;
#pragma unroll
    for (int j = 0; j < 6; j++) {
        int c = lane + 32*j;
        dp[c] = (v[j] - m) * rstd * g[c] + b[c];
    }
}

// ---------------- register-tiled window attention (f32x2) ----------------
#define OQ 0
#define OK_ 4224
#define OV 8448
#define OS 13056
#define ORP 29952
#define ORID 30628
#define ATTN_SMEM_F 30756

__global__ __launch_bounds__(256)
void attn2_kernel(const float* __restrict__ rpb, int shifted)
{
    extern __shared__ float sm[];
    float* Qt = sm + OQ;
    float* Kt = sm + OK_;
    float* Vs = sm + OV;
    float* Ss = sm + OS;
    float* rpb_s = sm + ORP;
    int* rid_s = (int*)(sm + ORID);

    const int win = blockIdx.x;
    const int hh  = blockIdx.y;
    const int t = threadIdx.x;
    const int tx = t & 15, ty = t >> 4;
    const float scale = 0.1767766952966369f;

    for (int e = t; e < 4096; e += 256) {
        int n = e >> 5, d = e & 31;
        size_t base = ((size_t)(win * 128 + n)) * (3 * C) + hh * 32 + d;
        Qt[d * 132 + n] = g_qkv[base] * scale;
        Kt[d * 132 + n] = g_qkv[base + C];
        Vs[n * 36 + d]  = g_qkv[base + 2 * C];
    }
    for (int e = t; e < TBL; e += 256) rpb_s[e] = rpb[e * HEADS + hh];
    int wloc = win & 255;
    int zw = wloc >> 4, hw = (wloc >> 2) & 3, ww = wloc & 3;
    if (shifted && t < 128) {
        int z = zw * 2 + (t >> 6), h = hw * 8 + ((t >> 3) & 7), w = ww * 8 + (t & 7);
        rid_s[t] = (z < 30 ? 0 : (z < 31 ? 1 : 2)) * 9
                 + (h < 24 ? 0 : (h < 28 ? 1 : 2)) * 3
                 + (w < 24 ? 0 : (w < 28 ? 1 : 2));
    }
    __syncthreads();

    ull acc[8][4];
#pragma unroll
    for (int r = 0; r < 8; r++)
#pragma unroll
        for (int j = 0; j < 4; j++) acc[r][j] = 0ull;
#pragma unroll 4
    for (int d = 0; d < 32; d++) {
        float4 q0 = *(const float4*)&Qt[d*132 + ty*4];
        float4 q1 = *(const float4*)&Qt[d*132 + 64 + ty*4];
        ulonglong2 k01 = *(const ulonglong2*)&Kt[d*132 + tx*4];
        ulonglong2 k23 = *(const ulonglong2*)&Kt[d*132 + 64 + tx*4];
        ull kp[4] = {k01.x, k01.y, k23.x, k23.y};
        float qf[8] = {q0.x, q0.y, q0.z, q0.w, q1.x, q1.y, q1.z, q1.w};
#pragma unroll
        for (int r = 0; r < 8; r++) {
            ull qd = dup2(qf[r]);
#pragma unroll
            for (int j = 0; j < 4; j++) fma2(acc[r][j], qd, kp[j]);
        }
    }
#pragma unroll
    for (int rr = 0; rr < 8; rr++) {
        int n = (rr < 4 ? ty*4 + rr : 64 + ty*4 + rr - 4);
        int zn = n >> 6, hn = (n >> 3) & 7, wn = n & 7;
        int ridn = shifted ? rid_s[n] : 0;
#pragma unroll
        for (int j = 0; j < 4; j++) {
            float2 v = unpack2(acc[rr][j]);
            int mb = (j < 2 ? tx*4 + 2*j : 64 + tx*4 + 2*(j - 2));
            {
                int m = mb;
                int zm = m >> 6, hm = (m >> 3) & 7, wm = m & 7;
                int idx = (zn - zm + 1) * 225 + (hn - hm + 7) * 15 + (wn - wm + 7);
                v.x += rpb_s[idx];
                if (shifted && rid_s[m] != ridn) v.x -= 100.0f;
            }
            {
                int m = mb + 1;
                int zm = m >> 6, hm = (m >> 3) & 7, wm = m & 7;
                int idx = (zn - zm + 1) * 225 + (hn - hm + 7) * 15 + (wn - wm + 7);
                v.y += rpb_s[idx];
                if (shifted && rid_s[m] != ridn) v.y -= 100.0f;
            }
            *(float2*)&Ss[n * 132 + mb] = v;
        }
    }
    __syncthreads();

    {
        int n = t >> 1, half = t & 1;
        float* row = &Ss[n * 132 + half * 64];
        float mx = -1e30f;
#pragma unroll
        for (int j = 0; j < 16; j++) {
            float4 v = *(const float4*)&row[j * 4];
            mx = fmaxf(mx, fmaxf(fmaxf(v.x, v.y), fmaxf(v.z, v.w)));
        }
        mx = fmaxf(mx, __shfl_xor_sync(0xffffffffu, mx, 1));
        float sum = 0.f;
#pragma unroll
        for (int j = 0; j < 16; j++) {
            float4 v = *(float4*)&row[j * 4];
            v.x = __expf(v.x - mx); v.y = __expf(v.y - mx);
            v.z = __expf(v.z - mx); v.w = __expf(v.w - mx);
            sum += v.x + v.y + v.z + v.w;
            *(float4*)&row[j * 4] = v;
        }
        sum += __shfl_xor_sync(0xffffffffu, sum, 1);
        float inv = 1.0f / sum;
#pragma unroll
        for (int j = 0; j < 16; j++) {
            float4 v = *(float4*)&row[j * 4];
            v.x *= inv; v.y *= inv; v.z *= inv; v.w *= inv;
            *(float4*)&row[j * 4] = v;
        }
    }
    __syncthreads();

    {
        int r0 = (t >> 2) * 2;
        int d0 = (t & 3) * 8;
        ull av[2][4];
#pragma unroll
        for (int i = 0; i < 2; i++)
#pragma unroll
            for (int j = 0; j < 4; j++) av[i][j] = 0ull;
#pragma unroll 8
        for (int m = 0; m < 128; m++) {
            float s0 = Ss[r0 * 132 + m];
            float s1 = Ss[(r0 + 1) * 132 + m];
            ulonglong2 v01 = *(const ulonglong2*)&Vs[m * 36 + d0];
            ulonglong2 v23 = *(const ulonglong2*)&Vs[m * 36 + d0 + 4];
            ull sd0 = dup2(s0), sd1 = dup2(s1);
            fma2(av[0][0], sd0, v01.x); fma2(av[0][1], sd0, v01.y);
            fma2(av[0][2], sd0, v23.x); fma2(av[0][3], sd0, v23.y);
            fma2(av[1][0], sd1, v01.x); fma2(av[1][1], sd1, v01.y);
            fma2(av[1][2], sd1, v23.x); fma2(av[1][3], sd1, v23.y);
        }
#pragma unroll
        for (int i = 0; i < 2; i++) {
            float of[8];
#pragma unroll
            for (int j = 0; j < 4; j++) {
                float2 v = unpack2(av[i][j]);
                of[2*j] = v.x; of[2*j+1] = v.y;
            }
            size_t ob = ((size_t)(win * 128 + r0 + i)) * C + hh * 32 + d0;
            *(float4*)&g_o[ob]     = make_float4(of[0], of[1], of[2], of[3]);
            *(float4*)&g_o[ob + 4] = make_float4(of[4], of[5], of[6], of[7]);
        }
    }
}

// ---------------- patch-embed gather / recon scatter ----------------
__global__ void gather_kernel(const float* __restrict__ x, float* __restrict__ xg)
{
    int idx = blockIdx.x * blockDim.x + threadIdx.x;
    if (idx >= NPOS * 128) return;
    int t = idx & 127, pos = idx >> 7;
    int w = pos & 31, h = (pos >> 5) & 31, z = (pos >> 10) & 31, b = pos >> 15;
    int c4 = t >> 5, i = (t >> 4) & 1, j = (t >> 2) & 3, k = t & 3;
    xg[idx] = x[((((size_t)b * 4 + c4) * 64 + 2 * z + i) * 128 + 4 * h + j) * 128 + 4 * w + k];
}

__global__ void scatter_kernel(const float* __restrict__ rec, const float* __restrict__ rec_b,
                               float* __restrict__ out)
{
    int idx = blockIdx.x * blockDim.x + threadIdx.x;
    if (idx >= NPOS * 128) return;
    int t = idx & 127, pos = idx >> 7;
    int w = pos & 31, h = (pos >> 5) & 31, z = (pos >> 10) & 31, b = pos >> 15;
    int o = t >> 5, i = (t >> 4) & 1, j = (t >> 2) & 3, k = t & 3;
    out[((((size_t)b * 4 + o) * 64 + 2 * z + i) * 128 + 4 * h + j) * 128 + 4 * w + k]
        = rec[idx] + rec_b[o];
}

// ---------------- host launcher ----------------
extern "C" void kernel_launch(void* const* d_in, const int* in_sizes, int n_in,
                              void* d_out, int out_size)
{
    const float* x       = (const float*)d_in[0];
    const float* pe_w    = (const float*)d_in[1];
    const float* pe_b    = (const float*)d_in[2];
    const float* pe_ln_g = (const float*)d_in[3];
    const float* pe_ln_b = (const float*)d_in[4];
    const float* ln1_g   = (const float*)d_in[5];
    const float* ln1_b   = (const float*)d_in[6];
    const float* qkv_w   = (const float*)d_in[7];
    const float* qkv_b   = (const float*)d_in[8];
    const float* proj_w  = (const float*)d_in[9];
    const float* proj_b  = (const float*)d_in[10];
    const float* rpb     = (const float*)d_in[11];
    const float* ln2_g   = (const float*)d_in[12];
    const float* ln2_b   = (const float*)d_in[13];
    const float* fc1_w   = (const float*)d_in[14];
    const float* fc1_b   = (const float*)d_in[15];
    const float* fc2_w   = (const float*)d_in[16];
    const float* fc2_b   = (const float*)d_in[17];
    const float* rec_w   = (const float*)d_in[18];
    const float* rec_b   = (const float*)d_in[19];
    float* out = (float*)d_out;

    float *e, *w, *qkv, *h, *o, *wt, *zeros;
    cudaGetSymbolAddress((void**)&e,     g_e);
    cudaGetSymbolAddress((void**)&w,     g_w);
    cudaGetSymbolAddress((void**)&qkv,   g_qkv);
    cudaGetSymbolAddress((void**)&h,     g_h);
    cudaGetSymbolAddress((void**)&o,     g_o);
    cudaGetSymbolAddress((void**)&wt,    g_wt);
    cudaGetSymbolAddress((void**)&zeros, g_zeros);

    const int ATTN_SMEM = ATTN_SMEM_F * (int)sizeof(float);
    cudaFuncSetAttribute(attn2_kernel, cudaFuncAttributeMaxDynamicSharedMemorySize, ATTN_SMEM);

    // ---- weight transposes ([K,N] -> [N,K]) ----
    for (int d = 0; d < DEPTH; d++) {
        transpose_w<<<(192*576 + 255)/256, 256>>>(qkv_w + (size_t)d*192*576, wt + QO  + (size_t)d*110592, 192, 576);
        transpose_w<<<(192*192 + 255)/256, 256>>>(proj_w + (size_t)d*192*192, wt + PO  + (size_t)d*36864, 192, 192);
        transpose_w<<<(192*768 + 255)/256, 256>>>(fc1_w + (size_t)d*192*768, wt + F1O + (size_t)d*147456, 192, 768);
        transpose_w<<<(768*192 + 255)/256, 256>>>(fc2_w + (size_t)d*768*192, wt + F2O + (size_t)d*147456, 768, 192);
    }
    transpose_w<<<(192*128 + 255)/256, 256>>>(rec_w, wt + RO, 192, 128);

    // ---- patch embed: gather -> GEMM (pe_w already [N=192, K=128]) -> LN ----
    gather_kernel<<<(NPOS * 128) / 256, 256>>>(x, h);
    gemm_mma<0,0><<<dim3(3, NPOS/128), 128>>>(h, pe_w, pe_b, w, 192, 128);
    ln2_kernel<<<NPOS / 8, 256>>>(w, e, pe_ln_g, pe_ln_b, 0);

    // ---- transformer layers ----
    for (int d = 0; d < DEPTH; d++) {
        int sh = d & 1;
        ln2_kernel<<<NPOS / 8, 256>>>(e, w, ln1_g + d * C, ln1_b + d * C, sh ? 2 : 1);
        gemm_mma<0,0><<<dim3(9, NPOS/128), 128>>>(
            w, wt + QO + (size_t)d*110592, qkv_b + d * 3 * C, qkv, 3 * C, C);
        attn2_kernel<<<dim3(B * NW, HEADS), 256, ATTN_SMEM>>>(rpb + (size_t)d * TBL * HEADS, sh);
        gemm_mma<0,0><<<dim3(3, NPOS/128), 128>>>(
            o, wt + PO + (size_t)d*36864, proj_b + d * C, w, C, C);
        // fused: e += unwindow(w); qkv = LN2(e)
        lnfuse_kernel<<<NPOS / 8, 256>>>(e, w, qkv, ln2_g + d * C, ln2_b + d * C, sh);
        gemm_mma<1,0><<<dim3(12, NPOS/128), 128>>>(
            qkv, wt + F1O + (size_t)d*147456, fc1_b + d * 4 * C, h, 4 * C, C);
        gemm_mma<0,1><<<dim3(3, NPOS/128), 128>>>(
            h, wt + F2O + (size_t)d*147456, fc2_b + d * C, e, C, 4 * C);
    }

    // ---- reconstruction ----
    gemm_mma<0,0><<<dim3(2, NPOS/128), 128>>>(e, wt + RO, zeros, qkv, 128, C);
    scatter_kernel<<<(NPOS * 128) / 256, 256>>>(qkv, rec_b, out);
}